// round 1
// baseline (speedup 1.0000x reference)
#include <cuda_runtime.h>
#include <math.h>

// B=64, N=17, T=512, C=64, H=4, DK=16
#define NB 64
#define NN 17
#define NT 512
#define NC 64

// Intermediate GAT output g[b,n,t,c] (flat per (b,n): t*64+c), 142.6 MB scratch.
__device__ float g_buf[(size_t)NB * NN * NT * NC];

__device__ __forceinline__ float gelu_exact(float v) {
    return 0.5f * v * (1.0f + erff(v * 0.70710678118654752440f));
}

// =====================================================================
// K1: GAT.  One block per (b, t-chunk of 8).  grid = 64*64 = 4096, 512 thr.
// smem: Ws[64][65] | xs[17][520] | hs[17][520] | av[32] | bias[289]
//       ss[544] ts[544] rowM[544] rowR[544] scl[544]   (= 24881 floats)
// =====================================================================
extern "C" __global__ void __launch_bounds__(512, 2)
gat_kernel(const float* __restrict__ x, const int* __restrict__ adj,
           const float* __restrict__ W, const float* __restrict__ a)
{
    extern __shared__ float sm[];
    float* Ws   = sm;            // 64*65
    float* xs   = Ws + 4160;     // 17*520
    float* hs   = xs + 8840;     // 17*520
    float* av   = hs + 8840;     // 32
    float* bias = av + 32;       // 17*17
    float* ss   = bias + 289;    // [tl*17+n]*4+h
    float* ts   = ss + 544;
    float* rowM = ts + 544;
    float* rowR = rowM + 544;
    float* scl  = rowR + 544;

    const int tid = threadIdx.x;
    const int b   = blockIdx.x >> 6;
    const int t0  = (blockIdx.x & 63) * 8;

    // ---- P0: loads (all coalesced) ----
    for (int i = tid; i < 4096; i += 512) Ws[(i >> 6) * 65 + (i & 63)] = W[i];
    const float* xblk = x + (size_t)(b * NN) * 32768 + t0 * 64;
    for (int i = tid; i < 17 * 512; i += 512) {
        int n = i >> 9, f = i & 511;
        xs[n * 520 + f] = xblk[(size_t)n * 32768 + f];
    }
    if (tid < 32) av[tid] = a[tid];
    for (int i = tid; i < 289; i += 512)
        bias[i] = (adj[b * 289 + i] == 0) ? -1e9f : 0.0f;
    __syncthreads();

    // ---- P1: h = h0 @ W^T (register-tiled 4o x 5pairs) ----
    {
        const int og = tid & 15;     // o = og + 16*i
        const int pg = tid >> 4;     // pair = pg + 32*j ;  pair p = tl*17+n
        float acc[4][5];
        int   pb[5];
        int   pvld[5];
        #pragma unroll
        for (int j = 0; j < 5; j++) {
            int p = pg + 32 * j;
            pvld[j] = (p < 136);
            int pp = pvld[j] ? p : 0;
            int n = pp % 17, tl = pp / 17;
            pb[j] = n * 520 + tl * 64;
            #pragma unroll
            for (int i = 0; i < 4; i++) acc[i][j] = 0.0f;
        }
        #pragma unroll 8
        for (int c = 0; c < 64; c++) {
            float w0 = Ws[ og        * 65 + c];
            float w1 = Ws[(og + 16)  * 65 + c];
            float w2 = Ws[(og + 32)  * 65 + c];
            float w3 = Ws[(og + 48)  * 65 + c];
            #pragma unroll
            for (int j = 0; j < 5; j++) {
                float xv = xs[pb[j] + c];
                acc[0][j] = fmaf(w0, xv, acc[0][j]);
                acc[1][j] = fmaf(w1, xv, acc[1][j]);
                acc[2][j] = fmaf(w2, xv, acc[2][j]);
                acc[3][j] = fmaf(w3, xv, acc[3][j]);
            }
        }
        #pragma unroll
        for (int j = 0; j < 5; j++) if (pvld[j]) {
            #pragma unroll
            for (int i = 0; i < 4; i++)
                hs[pb[j] + og + 16 * i] = acc[i][j];
        }
    }
    __syncthreads();

    // ---- P2: s,t per (tl,n,h) ----
    for (int q = tid; q < 544; q += 512) {
        int p = q >> 2, h = q & 3;
        int n = p % 17, tl = p / 17;
        const float* hrow = hs + n * 520 + tl * 64 + h * 16;
        float sv = 0.0f, tv = 0.0f;
        #pragma unroll
        for (int d = 0; d < 16; d++) {
            sv = fmaf(hrow[d], av[d], sv);
            tv = fmaf(hrow[d], av[16 + d], tv);
        }
        ss[q] = sv; ts[q] = tv;
    }
    __syncthreads();

    // ---- P3: per-row softmax stats over j (row = (tl,i,h)) ----
    for (int q = tid; q < 544; q += 512) {
        int h = q & 3, p = q >> 2;
        int i = p % 17, tl = p / 17;
        float sv = ss[q];
        const float* tsr = ts + (tl * 17) * 4 + h;   // stride 4 over j
        const float* br  = bias + i * 17;
        float M = -3.4e38f;
        #pragma unroll
        for (int j = 0; j < 17; j++) {
            float e = sv + tsr[j * 4];
            e = (e > 0.0f) ? e : 0.2f * e;
            e += br[j];
            M = fmaxf(M, e);
        }
        float S = 0.0f;
        #pragma unroll
        for (int j = 0; j < 17; j++) {
            float e = sv + tsr[j * 4];
            e = (e > 0.0f) ? e : 0.2f * e;
            e += br[j];
            S += __expf(e - M);
        }
        rowM[q] = M;
        rowR[q] = 1.0f / S;
    }
    __syncthreads();

    // ---- P4: scale[tl,j,h] = sum_i alpha[i,j,h] ----
    for (int q = tid; q < 544; q += 512) {
        int h = q & 3, p = q >> 2;
        int jj = p % 17, tl = p / 17;
        float tv = ts[q];
        float acc = 0.0f;
        #pragma unroll
        for (int i = 0; i < 17; i++) {
            int qi = (tl * 17 + i) * 4 + h;
            float e = ss[qi] + tv;
            e = (e > 0.0f) ? e : 0.2f * e;
            e += bias[i * 17 + jj];
            acc += __expf(e - rowM[qi]) * rowR[qi];
        }
        scl[q] = acc;
    }
    __syncthreads();

    // ---- P5: g = h*scale + h0  -> store to g_buf (coalesced) ----
    float* gout = g_buf + (size_t)(b * NN) * 32768 + t0 * 64;
    for (int i = tid; i < 8704; i += 512) {
        int n = i >> 9, f = i & 511;
        int tl = f >> 6, o = f & 63, h = o >> 4;
        float gval = fmaf(hs[n * 520 + f], scl[(tl * 17 + n) * 4 + h],
                          xs[n * 520 + f]);
        gout[(size_t)n * 32768 + f] = gval;
    }
}

// =====================================================================
// K2: causal depthwise TCN x2 (on the reinterpreted [64,512] flat view)
//     + output transpose + permuted residual.
// One block per (b, tau-chunk of 8), all n & all conv-channels in block.
// smem: xs[17][520] | gss[1088][17] | cw[640]  (= 27976 floats)
// =====================================================================
extern "C" __global__ void __launch_bounds__(512, 2)
tcn_kernel(const float* __restrict__ x,
           const float* __restrict__ w1, const float* __restrict__ gamma1,
           const float* __restrict__ beta1,
           const float* __restrict__ w2, const float* __restrict__ gamma2,
           const float* __restrict__ beta2,
           float* __restrict__ out)
{
    extern __shared__ float sm[];
    float* xs  = sm;             // 17*520  residual source slab x[b,:,tau0:tau0+8,:]
    float* gss = xs + 8840;      // 1088 rows * 17 (14 used + pad)
    float* cw  = gss + 18496;    // [w1:192][g1:64][b1:64][w2:192][g2:64][b2:64]

    const int tid  = threadIdx.x;
    const int b    = blockIdx.x >> 6;
    const int tau0 = (blockIdx.x & 63) * 8;

    const float* xblk = x + (size_t)(b * NN) * 32768 + tau0 * 64;
    for (int i = tid; i < 17 * 512; i += 512) {
        int n = i >> 9, f = i & 511;
        xs[n * 520 + f] = xblk[(size_t)n * 32768 + f];
    }
    for (int i = tid; i < 640; i += 512) {
        float v;
        if      (i < 192) v = w1[i];
        else if (i < 256) v = gamma1[i - 192];
        else if (i < 320) v = beta1[i - 256];
        else if (i < 512) v = w2[i - 320];
        else if (i < 576) v = gamma2[i - 512];
        else              v = beta2[i - 576];
        cw[i] = v;
    }
    // g segments: row r = n*64+cc, need flat (cc*512 + tau0-6+j), j in [0,14)
    const float* gblk = g_buf + (size_t)(b * NN) * 32768;
    for (int i = tid; i < 1088 * 16; i += 512) {
        int r = i >> 4, j = i & 15;
        if (j < 14) {
            int tt = tau0 - 6 + j;
            int n = r >> 6, cc = r & 63;
            gss[r * 17 + j] =
                (tt >= 0) ? gblk[(size_t)n * 32768 + cc * 512 + tt] : 0.0f;
        }
    }
    __syncthreads();

    const float rsb = 0.9999950000374997f;   // 1/sqrt(1 + 1e-5)
    for (int r = tid; r < 1088; r += 512) {
        int n = r >> 6, cc = r & 63;
        float a0  = cw[cc * 3 + 0], a1 = cw[cc * 3 + 1], a2 = cw[cc * 3 + 2];
        float gs1 = cw[192 + cc] * rsb, bb1 = cw[256 + cc];
        float c0  = cw[320 + cc * 3], c1 = cw[320 + cc * 3 + 1],
              c2v = cw[320 + cc * 3 + 2];
        float gs2 = cw[512 + cc] * rsb, bb2 = cw[576 + cc];

        const float* gr = gss + r * 17;
        float y[14];
        // conv1 (dil 1) + BN + GELU; y index j <-> tt = tau0-6+j ; y(tt<0)=0
        #pragma unroll
        for (int j = 2; j < 14; j++) {
            int tt = tau0 - 6 + j;
            if (tt < 0) {
                y[j] = 0.0f;
            } else {
                float v = fmaf(a0, gr[j - 2], fmaf(a1, gr[j - 1], a2 * gr[j]));
                y[j] = gelu_exact(fmaf(v, gs1, bb1));
            }
        }
        // conv2 (dil 2) + BN + GELU, transpose-write + permuted residual
        int ns = r % 17, cs = r / 17;    // residual source (node, channel)
        float* orow = out + ((size_t)(b * NN + n) * 512 + tau0) * 64 + cc;
        #pragma unroll
        for (int k = 0; k < 8; k++) {
            int j = k + 6;
            float v = fmaf(c0, y[j - 4], fmaf(c1, y[j - 2], c2v * y[j]));
            float z = gelu_exact(fmaf(v, gs2, bb2));
            orow[(size_t)k * 64] = z + xs[ns * 520 + k * 64 + cs];
        }
    }
}

// =====================================================================
extern "C" void kernel_launch(void* const* d_in, const int* in_sizes, int n_in,
                              void* d_out, int out_size)
{
    const float* x   = (const float*)d_in[0];
    const int*   adj = (const int*)  d_in[1];
    const float* W   = (const float*)d_in[2];
    const float* a   = (const float*)d_in[3];
    const float* w1  = (const float*)d_in[4];
    const float* g1  = (const float*)d_in[5];
    const float* b1  = (const float*)d_in[6];
    const float* w2  = (const float*)d_in[7];
    const float* g2  = (const float*)d_in[8];
    const float* b2  = (const float*)d_in[9];
    float* out = (float*)d_out;

    const size_t sm1 = (size_t)24881 * 4;   // 97.2 KB
    const size_t sm2 = (size_t)27976 * 4;   // 109.3 KB
    cudaFuncSetAttribute(gat_kernel, cudaFuncAttributeMaxDynamicSharedMemorySize, (int)sm1);
    cudaFuncSetAttribute(tcn_kernel, cudaFuncAttributeMaxDynamicSharedMemorySize, (int)sm2);

    gat_kernel<<<4096, 512, sm1>>>(x, adj, W, a);
    tcn_kernel<<<4096, 512, sm2>>>(x, w1, g1, b1, w2, g2, b2, out);
}

// round 2
// speedup vs baseline: 1.0144x; 1.0144x over previous
#include <cuda_runtime.h>
#include <math.h>

// B=64, N=17, T=512, C=64, H=4, DK=16
#define NB 64
#define NN 17
#define NT 512
#define NC 64

// Intermediate GAT output g[b,n,t,c] (flat per (b,n): t*64+c), 142.6 MB scratch.
__device__ float g_buf[(size_t)NB * NN * NT * NC];

// ---- packed fp32x2 helpers (Blackwell) ----
__device__ __forceinline__ unsigned long long pack2(float lo, float hi) {
    unsigned long long r;
    asm("mov.b64 %0,{%1,%2};" : "=l"(r) : "f"(lo), "f"(hi));
    return r;
}
__device__ __forceinline__ void unpack2(unsigned long long v, float& lo, float& hi) {
    asm("mov.b64 {%0,%1},%2;" : "=f"(lo), "=f"(hi) : "l"(v));
}
__device__ __forceinline__ unsigned long long fma2(unsigned long long a,
                                                   unsigned long long b,
                                                   unsigned long long c) {
    unsigned long long d;
    asm("fma.rn.f32x2 %0,%1,%2,%3;" : "=l"(d) : "l"(a), "l"(b), "l"(c));
    return d;
}

// Branchless erf-based GELU (Abramowitz-Stegun 7.1.26, |abs err| <= 1.5e-7).
__device__ __forceinline__ float gelu_fast(float v) {
    float av = fabsf(v);
    float s  = av * 0.70710678118654752440f;
    float d  = fmaf(0.3275911f, s, 1.0f);
    float t;
    asm("rcp.approx.f32 %0,%1;" : "=f"(t) : "f"(d));
    float e  = __expf(-s * s);
    float p  = fmaf(1.061405429f, t, -1.453152027f);
    p = fmaf(p, t, 1.421413741f);
    p = fmaf(p, t, -0.284496736f);
    p = fmaf(p, t, 0.254829592f);
    p = p * t;
    float u = fmaf(-p, e, 1.0f);          // erf(|v|/sqrt(2))
    return fmaf(0.5f * av, u, 0.5f * v);  // 0.5v + 0.5|v|erf
}

// =====================================================================
// K1: GAT.  One block per (b, t-chunk of 8).  grid = 64*64 = 4096, 512 thr.
// smem floats: Wt[64][66]=4224 | xs 17*528=8976 | hs 8976 | av 32 |
//              bias 289 | ss/ts/rowM/rowR/scl 544 each  (= 25217)
// xs/hs addr(n,f) = n*528 + (f>>6)*66 + (f&63)
// =====================================================================
extern "C" __global__ void __launch_bounds__(512, 2)
gat_kernel(const float* __restrict__ x, const int* __restrict__ adj,
           const float* __restrict__ W, const float* __restrict__ a)
{
    extern __shared__ float sm[];
    float* Wt   = sm;            // transposed: Wt[c*66 + o] = W[o][c]
    float* xs   = Wt + 4224;
    float* hs   = xs + 8976;
    float* av   = hs + 8976;
    float* bias = av + 32;
    float* ss   = bias + 289;
    float* ts   = ss + 544;
    float* rowM = ts + 544;
    float* rowR = rowM + 544;
    float* scl  = rowR + 544;

    const int tid = threadIdx.x;
    const int b   = blockIdx.x >> 6;
    const int t0  = (blockIdx.x & 63) * 8;

    // ---- P0: loads ----
    for (int i = tid; i < 4096; i += 512) {
        int o = i >> 6, c = i & 63;
        Wt[c * 66 + o] = W[i];
    }
    const float* xblk = x + (size_t)(b * NN) * 32768 + t0 * 64;
    for (int i = tid; i < 17 * 512; i += 512) {
        int n = i >> 9, f = i & 511;
        xs[n * 528 + (f >> 6) * 66 + (f & 63)] = xblk[(size_t)n * 32768 + f];
    }
    if (tid < 32) av[tid] = a[tid];
    for (int i = tid; i < 289; i += 512)
        bias[i] = (adj[b * 289 + i] == 0) ? -1e9f : 0.0f;
    __syncthreads();

    // ---- P1: h = h0 @ W^T ; packed f32x2 over output pairs ----
    {
        const int og = tid & 15;     // output pairs (2og,2og+1) and (+32)
        const int pg = tid >> 4;     // p = pg + 32*j, p = tl*17+n
        unsigned long long acc[2][5];
        int pb[5], pvld[5];
        #pragma unroll
        for (int j = 0; j < 5; j++) {
            int p = pg + 32 * j;
            pvld[j] = (p < 136);
            int pp = pvld[j] ? p : 0;
            int n = pp % 17, tl = pp / 17;
            pb[j] = n * 528 + tl * 66;
            acc[0][j] = 0ULL; acc[1][j] = 0ULL;
        }
        const unsigned long long* w0p =
            (const unsigned long long*)(Wt + 2 * og);
        const unsigned long long* w1p =
            (const unsigned long long*)(Wt + 2 * og + 32);
        #pragma unroll 8
        for (int c = 0; c < 64; c++) {
            unsigned long long w0 = w0p[c * 33];   // 66 floats = 33 u64
            unsigned long long w1 = w1p[c * 33];
            #pragma unroll
            for (int j = 0; j < 5; j++) {
                float xv = xs[pb[j] + c];
                unsigned long long xv2 = pack2(xv, xv);
                acc[0][j] = fma2(w0, xv2, acc[0][j]);
                acc[1][j] = fma2(w1, xv2, acc[1][j]);
            }
        }
        #pragma unroll
        for (int j = 0; j < 5; j++) if (pvld[j]) {
            float lo, hi;
            unpack2(acc[0][j], lo, hi);
            hs[pb[j] + 2 * og]      = lo;
            hs[pb[j] + 2 * og + 1]  = hi;
            unpack2(acc[1][j], lo, hi);
            hs[pb[j] + 2 * og + 32] = lo;
            hs[pb[j] + 2 * og + 33] = hi;
        }
    }
    __syncthreads();

    // ---- P2: s,t per (tl,n,h) ----
    for (int q = tid; q < 544; q += 512) {
        int p = q >> 2, h = q & 3;
        int n = p % 17, tl = p / 17;
        const float* hrow = hs + n * 528 + tl * 66 + h * 16;
        float sv = 0.0f, tv = 0.0f;
        #pragma unroll
        for (int d = 0; d < 16; d++) {
            sv = fmaf(hrow[d], av[d], sv);
            tv = fmaf(hrow[d], av[16 + d], tv);
        }
        ss[q] = sv; ts[q] = tv;
    }
    __syncthreads();

    // ---- P3: per-row softmax stats over j (row = (tl,i,h)) ----
    for (int q = tid; q < 544; q += 512) {
        int h = q & 3, p = q >> 2;
        int i = p % 17, tl = p / 17;
        float sv = ss[q];
        const float* tsr = ts + (tl * 17) * 4 + h;
        const float* br  = bias + i * 17;
        float M = -3.4e38f;
        float ev[17];
        #pragma unroll
        for (int j = 0; j < 17; j++) {
            float e = sv + tsr[j * 4];
            e = (e > 0.0f) ? e : 0.2f * e;
            e += br[j];
            ev[j] = e;
            M = fmaxf(M, e);
        }
        float S = 0.0f;
        #pragma unroll
        for (int j = 0; j < 17; j++) S += __expf(ev[j] - M);
        rowM[q] = M;
        rowR[q] = 1.0f / S;
    }
    __syncthreads();

    // ---- P4: scale[tl,j,h] = sum_i alpha[i,j,h] ----
    for (int q = tid; q < 544; q += 512) {
        int h = q & 3, p = q >> 2;
        int jj = p % 17, tl = p / 17;
        float tv = ts[q];
        float acc = 0.0f;
        #pragma unroll
        for (int i = 0; i < 17; i++) {
            int qi = (tl * 17 + i) * 4 + h;
            float e = ss[qi] + tv;
            e = (e > 0.0f) ? e : 0.2f * e;
            e += bias[i * 17 + jj];
            acc += __expf(e - rowM[qi]) * rowR[qi];
        }
        scl[q] = acc;
    }
    __syncthreads();

    // ---- P5: g = h*scale + h0 -> g_buf (coalesced) ----
    float* gout = g_buf + (size_t)(b * NN) * 32768 + t0 * 64;
    for (int i = tid; i < 8704; i += 512) {
        int n = i >> 9, f = i & 511;
        int tl = f >> 6, o = f & 63, h = o >> 4;
        int ad = n * 528 + tl * 66 + o;
        float gval = fmaf(hs[ad], scl[(tl * 17 + n) * 4 + h], xs[ad]);
        gout[(size_t)n * 32768 + f] = gval;
    }
}

// =====================================================================
// K2: causal depthwise TCN x2 on the reinterpreted [64,512] flat view
//     + output transpose + permuted residual.
// smem floats: xs 17*523=8891 | gss 1088*17=18496 | cw 640  (= 28027)
// =====================================================================
extern "C" __global__ void __launch_bounds__(512, 2)
tcn_kernel(const float* __restrict__ x,
           const float* __restrict__ w1, const float* __restrict__ gamma1,
           const float* __restrict__ beta1,
           const float* __restrict__ w2, const float* __restrict__ gamma2,
           const float* __restrict__ beta2,
           float* __restrict__ out)
{
    extern __shared__ float sm[];
    float* xs  = sm;             // [17][523] x slab (residual source)
    float* gss = xs + 8891;      // [1088][17] g halo segments
    float* cw  = gss + 18496;    // packed conv/BN params

    const int tid  = threadIdx.x;
    const int b    = blockIdx.x >> 6;
    const int tau0 = (blockIdx.x & 63) * 8;

    const float* xblk = x + (size_t)(b * NN) * 32768 + tau0 * 64;
    for (int i = tid; i < 17 * 512; i += 512) {
        int n = i >> 9, f = i & 511;
        xs[n * 523 + f] = xblk[(size_t)n * 32768 + f];
    }
    for (int i = tid; i < 640; i += 512) {
        float v;
        if      (i < 192) v = w1[i];
        else if (i < 256) v = gamma1[i - 192];
        else if (i < 320) v = beta1[i - 256];
        else if (i < 512) v = w2[i - 320];
        else if (i < 576) v = gamma2[i - 512];
        else              v = beta2[i - 576];
        cw[i] = v;
    }
    const float* gblk = g_buf + (size_t)(b * NN) * 32768;
    for (int i = tid; i < 1088 * 16; i += 512) {
        int r = i >> 4, j = i & 15;
        if (j < 14) {
            int tt = tau0 - 6 + j;
            int n = r >> 6, cc = r & 63;
            gss[r * 17 + j] =
                (tt >= 0) ? gblk[(size_t)n * 32768 + cc * 512 + tt] : 0.0f;
        }
    }
    __syncthreads();

    const float rsb = 0.9999950000374997f;   // 1/sqrt(1 + 1e-5)
    for (int r = tid; r < 1088; r += 512) {
        int n = r >> 6, cc = r & 63;
        float a0  = cw[cc * 3 + 0], a1 = cw[cc * 3 + 1], a2 = cw[cc * 3 + 2];
        float gs1 = cw[192 + cc] * rsb, bb1 = cw[256 + cc];
        float c0  = cw[320 + cc * 3], c1 = cw[320 + cc * 3 + 1],
              c2v = cw[320 + cc * 3 + 2];
        float gs2 = cw[512 + cc] * rsb, bb2 = cw[576 + cc];

        const float* gr = gss + r * 17;
        float y[14];
        #pragma unroll
        for (int j = 2; j < 14; j++) {
            int tt = tau0 - 6 + j;
            if (tt < 0) {
                y[j] = 0.0f;
            } else {
                float v = fmaf(a0, gr[j - 2], fmaf(a1, gr[j - 1], a2 * gr[j]));
                y[j] = gelu_fast(fmaf(v, gs1, bb1));
            }
        }
        int ns = r % 17, cs = r / 17;    // residual source (node, channel)
        float* orow = out + ((size_t)(b * NN + n) * 512 + tau0) * 64 + cc;
        #pragma unroll
        for (int k = 0; k < 8; k++) {
            int j = k + 6;
            float v = fmaf(c0, y[j - 4], fmaf(c1, y[j - 2], c2v * y[j]));
            float z = gelu_fast(fmaf(v, gs2, bb2));
            orow[(size_t)k * 64] = z + xs[ns * 523 + k * 64 + cs];
        }
    }
}

// =====================================================================
extern "C" void kernel_launch(void* const* d_in, const int* in_sizes, int n_in,
                              void* d_out, int out_size)
{
    const float* x   = (const float*)d_in[0];
    const int*   adj = (const int*)  d_in[1];
    const float* W   = (const float*)d_in[2];
    const float* a   = (const float*)d_in[3];
    const float* w1  = (const float*)d_in[4];
    const float* g1  = (const float*)d_in[5];
    const float* b1  = (const float*)d_in[6];
    const float* w2  = (const float*)d_in[7];
    const float* g2  = (const float*)d_in[8];
    const float* b2  = (const float*)d_in[9];
    float* out = (float*)d_out;

    const size_t sm1 = (size_t)25217 * 4;   // 98.5 KB
    const size_t sm2 = (size_t)28027 * 4;   // 109.5 KB
    cudaFuncSetAttribute(gat_kernel, cudaFuncAttributeMaxDynamicSharedMemorySize, (int)sm1);
    cudaFuncSetAttribute(tcn_kernel, cudaFuncAttributeMaxDynamicSharedMemorySize, (int)sm2);

    gat_kernel<<<4096, 512, sm1>>>(x, adj, W, a);
    tcn_kernel<<<4096, 512, sm2>>>(x, w1, g1, b1, w2, g2, b2, out);
}

// round 3
// speedup vs baseline: 1.4181x; 1.3979x over previous
#include <cuda_runtime.h>
#include <math.h>

// B=64, N=17, T=512, C=64, H=4, DK=16
#define NB 64
#define NN 17
#define NT 512
#define NC 64

// Intermediate GAT output g[b,n,t,c] (flat per (b,n): t*64+c), 142.6 MB scratch.
__device__ float g_buf[(size_t)NB * NN * NT * NC];

// ---- packed fp32x2 helpers (Blackwell) ----
__device__ __forceinline__ unsigned long long pack2(float lo, float hi) {
    unsigned long long r;
    asm("mov.b64 %0,{%1,%2};" : "=l"(r) : "f"(lo), "f"(hi));
    return r;
}
__device__ __forceinline__ void unpack2(unsigned long long v, float& lo, float& hi) {
    asm("mov.b64 {%0,%1},%2;" : "=f"(lo), "=f"(hi) : "l"(v));
}
__device__ __forceinline__ unsigned long long fma2(unsigned long long a,
                                                   unsigned long long b,
                                                   unsigned long long c) {
    unsigned long long d;
    asm("fma.rn.f32x2 %0,%1,%2,%3;" : "=l"(d) : "l"(a), "l"(b), "l"(c));
    return d;
}

// Branchless erf-based GELU (Abramowitz-Stegun 7.1.26, |abs err| <= 1.5e-7).
__device__ __forceinline__ float gelu_fast(float v) {
    float av = fabsf(v);
    float s  = av * 0.70710678118654752440f;
    float d  = fmaf(0.3275911f, s, 1.0f);
    float t;
    asm("rcp.approx.f32 %0,%1;" : "=f"(t) : "f"(d));
    float e  = __expf(-s * s);
    float p  = fmaf(1.061405429f, t, -1.453152027f);
    p = fmaf(p, t, 1.421413741f);
    p = fmaf(p, t, -0.284496736f);
    p = fmaf(p, t, 0.254829592f);
    p = p * t;
    float u = fmaf(-p, e, 1.0f);          // erf(|v|/sqrt(2))
    return fmaf(0.5f * av, u, 0.5f * v);  // 0.5v + 0.5|v|erf
}

// =====================================================================
// K1: GAT.  One block per (b, t-chunk of 8).  grid = 4096, 544 threads.
// smem floats: Wt[64][66]=4224 | xs 17*528=8976 | hs 8976 | av 32 |
//              bias 289 | ss/ts/rowM/rowR/scl 544 each  (= 25217)
// xs/hs addr(n,f) = n*528 + (f>>6)*66 + (f&63)
// =====================================================================
extern "C" __global__ void __launch_bounds__(544, 2)
gat_kernel(const float* __restrict__ x, const int* __restrict__ adj,
           const float* __restrict__ W, const float* __restrict__ a)
{
    extern __shared__ float sm[];
    float* Wt   = sm;            // transposed: Wt[c*66 + o] = W[o][c]
    float* xs   = Wt + 4224;
    float* hs   = xs + 8976;
    float* av   = hs + 8976;
    float* bias = av + 32;
    float* ss   = bias + 289;
    float* ts   = ss + 544;
    float* rowM = ts + 544;
    float* rowR = rowM + 544;
    float* scl  = rowR + 544;

    const int tid = threadIdx.x;
    const int b   = blockIdx.x >> 6;
    const int t0  = (blockIdx.x & 63) * 8;

    // ---- P0: loads ----
    for (int i = tid; i < 4096; i += 544) {
        int o = i >> 6, c = i & 63;
        Wt[c * 66 + o] = W[i];
    }
    const float* xblk = x + (size_t)(b * NN) * 32768 + t0 * 64;
    #pragma unroll
    for (int k = 0; k < 16; k++) {
        int i = tid + k * 544;
        int n = i >> 9, f = i & 511;
        xs[n * 528 + (f >> 6) * 66 + (f & 63)] = xblk[(size_t)n * 32768 + f];
    }
    if (tid < 32) av[tid] = a[tid];
    if (tid < 289)
        bias[tid] = (adj[b * 289 + tid] == 0) ? -1e9f : 0.0f;
    __syncthreads();

    // ---- P1: h = h0 @ W^T ; packed f32x2 over output pairs (4 pairs/thread) ----
    {
        const int og = tid & 15;     // output pairs (2og,2og+1) and (+32)
        const int pg = tid >> 4;     // p = pg + 34*j, p = tl*17+n, j<4
        unsigned long long acc[2][4];
        int pb[4];
        #pragma unroll
        for (int j = 0; j < 4; j++) {
            int p = pg + 34 * j;
            int n = p % 17, tl = p / 17;
            pb[j] = n * 528 + tl * 66;
            acc[0][j] = 0ULL; acc[1][j] = 0ULL;
        }
        const unsigned long long* w0p =
            (const unsigned long long*)(Wt + 2 * og);
        const unsigned long long* w1p =
            (const unsigned long long*)(Wt + 2 * og + 32);
        #pragma unroll 8
        for (int c = 0; c < 64; c++) {
            unsigned long long w0 = w0p[c * 33];   // 66 floats = 33 u64
            unsigned long long w1 = w1p[c * 33];
            #pragma unroll
            for (int j = 0; j < 4; j++) {
                float xv = xs[pb[j] + c];
                unsigned long long xv2 = pack2(xv, xv);
                acc[0][j] = fma2(w0, xv2, acc[0][j]);
                acc[1][j] = fma2(w1, xv2, acc[1][j]);
            }
        }
        #pragma unroll
        for (int j = 0; j < 4; j++) {
            float lo, hi;
            unpack2(acc[0][j], lo, hi);
            hs[pb[j] + 2 * og]      = lo;
            hs[pb[j] + 2 * og + 1]  = hi;
            unpack2(acc[1][j], lo, hi);
            hs[pb[j] + 2 * og + 32] = lo;
            hs[pb[j] + 2 * og + 33] = hi;
        }
    }
    __syncthreads();

    // ---- P2: s,t per (tl,n,h) ; one element per thread ----
    {
        int q = tid;
        int p = q >> 2, h = q & 3;
        int n = p % 17, tl = p / 17;
        const float* hrow = hs + n * 528 + tl * 66 + h * 16;
        float sv = 0.0f, tv = 0.0f;
        #pragma unroll
        for (int d = 0; d < 16; d++) {
            sv = fmaf(hrow[d], av[d], sv);
            tv = fmaf(hrow[d], av[16 + d], tv);
        }
        ss[q] = sv; ts[q] = tv;
    }
    __syncthreads();

    // ---- P3: per-row softmax stats over j (row = (tl,i,h)) ----
    {
        int q = tid;
        int h = q & 3, p = q >> 2;
        int i = p % 17, tl = p / 17;
        float sv = ss[q];
        const float* tsr = ts + (tl * 17) * 4 + h;
        const float* br  = bias + i * 17;
        float M = -3.4e38f;
        float ev[17];
        #pragma unroll
        for (int j = 0; j < 17; j++) {
            float e = sv + tsr[j * 4];
            e = (e > 0.0f) ? e : 0.2f * e;
            e += br[j];
            ev[j] = e;
            M = fmaxf(M, e);
        }
        float S = 0.0f;
        #pragma unroll
        for (int j = 0; j < 17; j++) S += __expf(ev[j] - M);
        rowM[q] = M;
        rowR[q] = 1.0f / S;
    }
    __syncthreads();

    // ---- P4: scale[tl,j,h] = sum_i alpha[i,j,h] ----
    {
        int q = tid;
        int h = q & 3, p = q >> 2;
        int jj = p % 17, tl = p / 17;
        float tv = ts[q];
        float acc = 0.0f;
        #pragma unroll
        for (int i = 0; i < 17; i++) {
            int qi = (tl * 17 + i) * 4 + h;
            float e = ss[qi] + tv;
            e = (e > 0.0f) ? e : 0.2f * e;
            e += bias[i * 17 + jj];
            acc += __expf(e - rowM[qi]) * rowR[qi];
        }
        scl[q] = acc;
    }
    __syncthreads();

    // ---- P5: g = h*scale + h0 -> g_buf (coalesced) ----
    float* gout = g_buf + (size_t)(b * NN) * 32768 + t0 * 64;
    #pragma unroll
    for (int k = 0; k < 16; k++) {
        int i = tid + k * 544;
        int n = i >> 9, f = i & 511;
        int tl = f >> 6, o = f & 63, h = o >> 4;
        int ad = n * 528 + tl * 66 + o;
        float gval = fmaf(hs[ad], scl[(tl * 17 + n) * 4 + h], xs[ad]);
        gout[(size_t)n * 32768 + f] = gval;
    }
}

// =====================================================================
// K2: causal depthwise TCN x2 on the reinterpreted [64,512] flat view
//     + output transpose + permuted residual.
// Block = (b, tau-chunk of 8, row-half).  544 threads, 1 row/thread.
// smem floats: xs 17*257=4369 | gss 544*17=9248 | cw 640  (= 14257 ~ 57KB)
// =====================================================================
extern "C" __global__ void __launch_bounds__(544, 3)
tcn_kernel(const float* __restrict__ x,
           const float* __restrict__ w1, const float* __restrict__ gamma1,
           const float* __restrict__ beta1,
           const float* __restrict__ w2, const float* __restrict__ gamma2,
           const float* __restrict__ beta2,
           float* __restrict__ out)
{
    extern __shared__ float sm[];
    float* xs  = sm;             // [17][8*32+pad] residual slab (cs half)
    float* gss = xs + 4369;      // [544][17] g halo segments
    float* cw  = gss + 9248;     // packed conv/BN params (640)

    const int tid  = threadIdx.x;
    const int bid  = blockIdx.x;
    const int h    = bid & 1;              // row half
    const int tau0 = ((bid >> 1) & 63) * 8;
    const int b    = bid >> 7;

    // residual slab: x[b, ns, tau0+k, h*32+csl], 4352 elems, 8 iters
    const float* xb = x + (size_t)b * NN * 32768 + (size_t)tau0 * 64 + h * 32;
    #pragma unroll
    for (int k = 0; k < 8; k++) {
        int i = tid + k * 544;
        int ns = i >> 8, rem = i & 255;
        int kk = rem >> 5, csl = rem & 31;
        xs[ns * 257 + kk * 32 + csl] =
            xb[(size_t)ns * 32768 + kk * 64 + csl];
    }
    for (int i = tid; i < 640; i += 544) {
        float v;
        if      (i < 192) v = w1[i];
        else if (i < 256) v = gamma1[i - 192];
        else if (i < 320) v = beta1[i - 256];
        else if (i < 512) v = w2[i - 320];
        else if (i < 576) v = gamma2[i - 512];
        else              v = beta2[i - 576];
        cw[i] = v;
    }
    // g halo: row rr (global rg = h*544+rr) needs flat cc*512 + tau0-6+j, j<14
    const float* gblk = g_buf + (size_t)b * NN * 32768;
    #pragma unroll
    for (int k = 0; k < 16; k++) {
        int i = tid + k * 544;
        int rr = i >> 4, j = i & 15;
        if (j < 14) {
            int rg = h * 544 + rr;
            int n = rg >> 6, cc = rg & 63;
            int tt = tau0 - 6 + j;
            gss[rr * 17 + j] =
                (tt >= 0) ? gblk[(size_t)n * 32768 + cc * 512 + tt] : 0.0f;
        }
    }
    __syncthreads();

    const float rsb = 0.9999950000374997f;   // 1/sqrt(1 + 1e-5)
    {
        const int rr = tid;
        const int rg = h * 544 + rr;
        const int n  = rg >> 6, cc = rg & 63;
        const float a0  = cw[cc * 3 + 0], a1 = cw[cc * 3 + 1],
                    a2  = cw[cc * 3 + 2];
        const float gs1 = cw[192 + cc] * rsb, bb1 = cw[256 + cc];
        const float* gr = gss + rr * 17;

        const int ns  = rg % 17;
        const int csl = rg / 17 - h * 32;
        float* orow = out + ((size_t)(b * NN + n) * 512 + tau0) * 64 + cc;

        float y[14];
        // conv1 (dil 1) + BN + GELU;  y index j <-> tt = tau0-6+j
        #pragma unroll
        for (int j = 2; j < 6; j++) {
            float v = fmaf(a0, gr[j - 2], fmaf(a1, gr[j - 1], a2 * gr[j]));
            float yy = gelu_fast(fmaf(v, gs1, bb1));
            y[j] = (tau0 - 6 + j >= 0) ? yy : 0.0f;
        }
        #pragma unroll
        for (int k = 0; k < 8; k++) {
            int j = k + 6;
            {
                float v = fmaf(a0, gr[j - 2], fmaf(a1, gr[j - 1], a2 * gr[j]));
                y[j] = gelu_fast(fmaf(v, gs1, bb1));   // tt = tau0+k >= 0 always
            }
            float c0  = cw[320 + cc * 3], c1 = cw[320 + cc * 3 + 1],
                  c2v = cw[320 + cc * 3 + 2];
            float gs2 = cw[512 + cc] * rsb, bb2 = cw[576 + cc];
            float v = fmaf(c0, y[j - 4], fmaf(c1, y[j - 2], c2v * y[j]));
            float z = gelu_fast(fmaf(v, gs2, bb2));
            orow[(size_t)k * 64] = z + xs[ns * 257 + k * 32 + csl];
        }
    }
}

// =====================================================================
extern "C" void kernel_launch(void* const* d_in, const int* in_sizes, int n_in,
                              void* d_out, int out_size)
{
    const float* x   = (const float*)d_in[0];
    const int*   adj = (const int*)  d_in[1];
    const float* W   = (const float*)d_in[2];
    const float* a   = (const float*)d_in[3];
    const float* w1  = (const float*)d_in[4];
    const float* g1  = (const float*)d_in[5];
    const float* b1  = (const float*)d_in[6];
    const float* w2  = (const float*)d_in[7];
    const float* g2  = (const float*)d_in[8];
    const float* b2  = (const float*)d_in[9];
    float* out = (float*)d_out;

    const size_t sm1 = (size_t)25217 * 4;   // 98.5 KB
    const size_t sm2 = (size_t)14257 * 4;   // 57.0 KB
    cudaFuncSetAttribute(gat_kernel, cudaFuncAttributeMaxDynamicSharedMemorySize, (int)sm1);
    cudaFuncSetAttribute(tcn_kernel, cudaFuncAttributeMaxDynamicSharedMemorySize, (int)sm2);

    gat_kernel<<<4096, 544, sm1>>>(x, adj, W, a);
    tcn_kernel<<<8192, 544, sm2>>>(x, w1, g1, b1, w2, g2, b2, out);
}

// round 5
// speedup vs baseline: 1.6911x; 1.1925x over previous
#include <cuda_runtime.h>
#include <math.h>

// B=64, N=17, T=512, C=64, H=4, DK=16
#define NB 64
#define NN 17
#define NT 512
#define NC 64

// Intermediate GAT output g[b,n,t,c] (flat per (b,n): t*64+c), 142.6 MB scratch.
__device__ float g_buf[(size_t)NB * NN * NT * NC];

// ---- packed fp32x2 helpers (Blackwell) ----
__device__ __forceinline__ unsigned long long pack2(float lo, float hi) {
    unsigned long long r;
    asm("mov.b64 %0,{%1,%2};" : "=l"(r) : "f"(lo), "f"(hi));
    return r;
}
__device__ __forceinline__ void unpack2(unsigned long long v, float& lo, float& hi) {
    asm("mov.b64 {%0,%1},%2;" : "=f"(lo), "=f"(hi) : "l"(v));
}
__device__ __forceinline__ unsigned long long fma2(unsigned long long a,
                                                   unsigned long long b,
                                                   unsigned long long c) {
    unsigned long long d;
    asm("fma.rn.f32x2 %0,%1,%2,%3;" : "=l"(d) : "l"(a), "l"(b), "l"(c));
    return d;
}

// Branchless erf-based GELU (Abramowitz-Stegun 7.1.26, |abs err| <= 1.5e-7).
__device__ __forceinline__ float gelu_fast(float v) {
    float av = fabsf(v);
    float s  = av * 0.70710678118654752440f;
    float d  = fmaf(0.3275911f, s, 1.0f);
    float t;
    asm("rcp.approx.f32 %0,%1;" : "=f"(t) : "f"(d));
    float e  = __expf(-s * s);
    float p  = fmaf(1.061405429f, t, -1.453152027f);
    p = fmaf(p, t, 1.421413741f);
    p = fmaf(p, t, -0.284496736f);
    p = fmaf(p, t, 0.254829592f);
    p = p * t;
    float u = fmaf(-p, e, 1.0f);          // erf(|v|/sqrt(2))
    return fmaf(0.5f * av, u, 0.5f * v);  // 0.5v + 0.5|v|erf
}

// =====================================================================
// K1: GAT.  One block per (b, t-chunk of 8).  grid 4096, 544 threads.
// h lives in registers (16 floats/thread); no hs array.
// smem floats: Wt 64*66=4224 | xs 17*528=8976 | av 32 | bias 289 |
//              ss/ts/rowM/rowR/scl 544 each  (= 16241 ~ 63.5KB) -> 3 blk/SM
// xs addr(n,f) = n*528 + (f>>6)*66 + (f&63)   (f = tl*64 + c)
// =====================================================================
extern "C" __global__ void __launch_bounds__(544, 3)
gat_kernel(const float* __restrict__ x, const int* __restrict__ adj,
           const float* __restrict__ W, const float* __restrict__ a)
{
    extern __shared__ float sm[];
    float* Wt   = sm;            // transposed: Wt[c*66 + o] = W[o][c]
    float* xs   = Wt + 4224;
    float* av   = xs + 8976;
    float* bias = av + 32;
    float* ss   = bias + 289;
    float* ts   = ss + 544;
    float* rowM = ts + 544;
    float* rowR = rowM + 544;
    float* scl  = rowR + 544;

    const int tid = threadIdx.x;
    const int b   = blockIdx.x >> 6;
    const int t0  = (blockIdx.x & 63) * 8;

    // ---- P0: loads ----
    for (int i = tid; i < 4096; i += 544) {
        int o = i >> 6, c = i & 63;
        Wt[c * 66 + o] = W[i];
    }
    {   // x slab as float2: 4352 float2, 8 iters
        const float2* xb2 = (const float2*)x + (size_t)b * 278528 + t0 * 32;
        #pragma unroll
        for (int k = 0; k < 8; k++) {
            int i = tid + k * 544;
            int n = i >> 8, rem = i & 255;     // 256 float2 per node
            int tl = rem >> 5, cpl = rem & 31;
            float2 v = xb2[(size_t)n * 16384 + tl * 32 + cpl];
            ((float2*)xs)[n * 264 + tl * 33 + cpl] = v;
        }
    }
    if (tid < 32) av[tid] = a[tid];
    if (tid < 289)
        bias[tid] = (adj[b * 289 + tid] == 0) ? -1e9f : 0.0f;
    __syncthreads();

    // ---- P1: h = h0 @ W^T ; packed f32x2, h kept in registers ----
    const int og = tid & 15;     // output pairs (2og,2og+1) and (+32,+33)
    const int pg = tid >> 4;     // p = pg + 34*j, p = tl*17+n
    unsigned long long acc[2][4];
    int pb[4];
    {
        #pragma unroll
        for (int j = 0; j < 4; j++) {
            int p = pg + 34 * j;
            int n = p % 17, tl = p / 17;
            pb[j] = n * 528 + tl * 66;
            acc[0][j] = 0ULL; acc[1][j] = 0ULL;
        }
        const unsigned long long* w0p =
            (const unsigned long long*)(Wt + 2 * og);
        const unsigned long long* w1p =
            (const unsigned long long*)(Wt + 2 * og + 32);
        #pragma unroll 4
        for (int c = 0; c < 64; c++) {
            unsigned long long w0 = w0p[c * 33];   // 66 floats = 33 u64
            unsigned long long w1 = w1p[c * 33];
            #pragma unroll
            for (int j = 0; j < 4; j++) {
                float xv = xs[pb[j] + c];
                unsigned long long xv2 = pack2(xv, xv);
                acc[0][j] = fma2(w0, xv2, acc[0][j]);
                acc[1][j] = fma2(w1, xv2, acc[1][j]);
            }
        }
    }

    // ---- P2: s,t via in-warp 8-lane reductions of register h ----
    {
        const int h0 = og >> 3;            // head of pair (2og,2og+1); +2 for hi
        const int d0 = 2 * (og & 7);       // a-index within head
        const float aS0 = av[d0],      aS1 = av[d0 + 1];
        const float aT0 = av[16 + d0], aT1 = av[17 + d0];
        #pragma unroll
        for (int j = 0; j < 4; j++) {
            float hlo0, hhi0, hlo1, hhi1;
            unpack2(acc[0][j], hlo0, hhi0);
            unpack2(acc[1][j], hlo1, hhi1);
            float sA = fmaf(hlo0, aS0, hhi0 * aS1);
            float tA = fmaf(hlo0, aT0, hhi0 * aT1);
            float sB = fmaf(hlo1, aS0, hhi1 * aS1);
            float tB = fmaf(hlo1, aT0, hhi1 * aT1);
            #pragma unroll
            for (int w = 4; w; w >>= 1) {
                sA += __shfl_xor_sync(0xffffffffu, sA, w);
                tA += __shfl_xor_sync(0xffffffffu, tA, w);
                sB += __shfl_xor_sync(0xffffffffu, sB, w);
                tB += __shfl_xor_sync(0xffffffffu, tB, w);
            }
            if ((og & 7) == 0) {
                int p = pg + 34 * j;
                ss[p * 4 + h0]     = sA;
                ss[p * 4 + h0 + 2] = sB;
                ts[p * 4 + h0]     = tA;
                ts[p * 4 + h0 + 2] = tB;
            }
        }
    }
    __syncthreads();

    // ---- P3: per-row softmax stats over j (row = (tl,i,h)) ----
    {
        int q = tid;
        int h = q & 3, p = q >> 2;
        int i = p % 17, tl = p / 17;
        float sv = ss[q];
        const float* tsr = ts + (tl * 17) * 4 + h;
        const float* br  = bias + i * 17;
        float M = -3.4e38f;
        float ev[17];
        #pragma unroll
        for (int j = 0; j < 17; j++) {
            float e = sv + tsr[j * 4];
            e = (e > 0.0f) ? e : 0.2f * e;
            e += br[j];
            ev[j] = e;
            M = fmaxf(M, e);
        }
        float S = 0.0f;
        #pragma unroll
        for (int j = 0; j < 17; j++) S += __expf(ev[j] - M);
        rowM[q] = M;
        rowR[q] = 1.0f / S;
    }
    __syncthreads();

    // ---- P4: scale[tl,j,h] = sum_i alpha[i,j,h] ----
    {
        int q = tid;
        int h = q & 3, p = q >> 2;
        int jj = p % 17, tl = p / 17;
        float tv = ts[q];
        float acc4 = 0.0f;
        #pragma unroll
        for (int i = 0; i < 17; i++) {
            int qi = (tl * 17 + i) * 4 + h;
            float e = ss[qi] + tv;
            e = (e > 0.0f) ? e : 0.2f * e;
            e += bias[i * 17 + jj];
            acc4 += __expf(e - rowM[qi]) * rowR[qi];
        }
        scl[q] = acc4;
    }
    __syncthreads();

    // ---- P5: g = h*scale + h0 -> g_buf directly from registers ----
    {
        const int h0 = og >> 3;
        float* gbase = g_buf + (size_t)b * 557056 + t0 * 64;
        #pragma unroll
        for (int j = 0; j < 4; j++) {
            int p = pg + 34 * j;
            int n = p % 17, tl = p / 17;
            float sc0 = scl[(tl * 17 + n) * 4 + h0];
            float sc2 = scl[(tl * 17 + n) * 4 + h0 + 2];
            float hlo0, hhi0, hlo1, hhi1;
            unpack2(acc[0][j], hlo0, hhi0);
            unpack2(acc[1][j], hlo1, hhi1);
            float2 x0 = *(const float2*)&xs[pb[j] + 2 * og];
            float2 x1 = *(const float2*)&xs[pb[j] + 2 * og + 32];
            float2 g0, g1;
            g0.x = fmaf(hlo0, sc0, x0.x);
            g0.y = fmaf(hhi0, sc0, x0.y);
            g1.x = fmaf(hlo1, sc2, x1.x);
            g1.y = fmaf(hhi1, sc2, x1.y);
            int base = n * 32768 + tl * 64;
            *(float2*)(gbase + base + 2 * og)      = g0;
            *(float2*)(gbase + base + 2 * og + 32) = g1;
        }
    }
}

// =====================================================================
// K2: causal depthwise TCN x2 on the reinterpreted [64,512] flat view
//     + output transpose + permuted residual.
// Block = (b, tau-chunk of 8, row-half).  544 threads, 1 row/thread.
// smem floats: xs 17*258=4386 | gss 544*18=9792 | cw 640  (= 14818 ~ 58KB)
// =====================================================================
extern "C" __global__ void __launch_bounds__(544, 3)
tcn_kernel(const float* __restrict__ x,
           const float* __restrict__ w1, const float* __restrict__ gamma1,
           const float* __restrict__ beta1,
           const float* __restrict__ w2, const float* __restrict__ gamma2,
           const float* __restrict__ beta2,
           float* __restrict__ out)
{
    extern __shared__ float sm[];
    float* xs  = sm;             // [17][258] residual slab (cs half)
    float* gss = xs + 4386;      // [544][18] g halo segments (14 used)
    float* cw  = gss + 9792;     // packed conv/BN params (640)

    const int tid  = threadIdx.x;
    const int bid  = blockIdx.x;
    const int h    = bid & 1;              // row half
    const int tau0 = ((bid >> 1) & 63) * 8;
    const int b    = bid >> 7;

    // residual slab via float2: 2176 float2, 4 iters
    {
        const float2* xb2 = (const float2*)x + (size_t)b * 278528
                            + tau0 * 32 + h * 16;
        #pragma unroll
        for (int k = 0; k < 4; k++) {
            int i = tid + k * 544;
            int ns = i >> 7, rem = i & 127;     // 128 float2 per node
            int kk = rem >> 4, cpl = rem & 15;
            float2 v = xb2[(size_t)ns * 16384 + kk * 32 + cpl];
            ((float2*)xs)[ns * 129 + rem] = v;
        }
    }
    for (int i = tid; i < 640; i += 544) {
        float v;
        if      (i < 192) v = w1[i];
        else if (i < 256) v = gamma1[i - 192];
        else if (i < 320) v = beta1[i - 256];
        else if (i < 512) v = w2[i - 320];
        else if (i < 576) v = gamma2[i - 512];
        else              v = beta2[i - 576];
        cw[i] = v;
    }
    // g halo via float2: row rr needs flat cc*512 + tau0-6+j, j<14 (7 float2)
    {
        const float2* gblk2 = (const float2*)(g_buf) + (size_t)b * 278528;
        const int toff = (tau0 - 6) >> 1;   // tau0-6 even
        #pragma unroll
        for (int k = 0; k < 8; k++) {
            int i = tid + k * 544;
            int rr = i >> 3, jj = i & 7;
            if (jj < 7) {
                int rg = h * 544 + rr;
                int n = rg >> 6, cc = rg & 63;
                int tt = tau0 - 6 + 2 * jj;
                float2 v;
                if (tt >= 0)
                    v = gblk2[n * 16384 + cc * 256 + toff + jj];
                else { v.x = 0.0f; v.y = 0.0f; }
                ((float2*)gss)[rr * 9 + jj] = v;
            }
        }
    }
    __syncthreads();

    const float rsb = 0.9999950000374997f;   // 1/sqrt(1 + 1e-5)
    {
        const int rr = tid;
        const int rg = h * 544 + rr;
        const int n  = rg >> 6, cc = rg & 63;
        const float a0  = cw[cc * 3 + 0], a1 = cw[cc * 3 + 1],
                    a2  = cw[cc * 3 + 2];
        const float gs1 = cw[192 + cc] * rsb, bb1 = cw[256 + cc];
        const float c0  = cw[320 + cc * 3], c1 = cw[320 + cc * 3 + 1],
                    c2v = cw[320 + cc * 3 + 2];
        const float gs2 = cw[512 + cc] * rsb, bb2 = cw[576 + cc];
        const float* gr = gss + rr * 18;

        const int ns  = rg % 17;
        const int csl = rg / 17 - h * 32;
        float* orow = out + ((size_t)(b * NN + n) * 512 + tau0) * 64 + cc;

        float y[14];
        #pragma unroll
        for (int j = 2; j < 14; j++) {
            float v = fmaf(a0, gr[j - 2], fmaf(a1, gr[j - 1], a2 * gr[j]));
            y[j] = gelu_fast(fmaf(v, gs1, bb1));
        }
        if (tau0 == 0) { y[2] = 0.0f; y[3] = 0.0f; y[4] = 0.0f; y[5] = 0.0f; }

        #pragma unroll
        for (int k = 0; k < 8; k++) {
            int j = k + 6;
            float v = fmaf(c0, y[j - 4], fmaf(c1, y[j - 2], c2v * y[j]));
            float z = gelu_fast(fmaf(v, gs2, bb2));
            orow[(size_t)k * 64] = z + xs[ns * 258 + k * 32 + csl];
        }
    }
}

// =====================================================================
extern "C" void kernel_launch(void* const* d_in, const int* in_sizes, int n_in,
                              void* d_out, int out_size)
{
    const float* x   = (const float*)d_in[0];
    const int*   adj = (const int*)  d_in[1];
    const float* W   = (const float*)d_in[2];
    const float* a   = (const float*)d_in[3];
    const float* w1  = (const float*)d_in[4];
    const float* g1  = (const float*)d_in[5];
    const float* b1  = (const float*)d_in[6];
    const float* w2  = (const float*)d_in[7];
    const float* g2  = (const float*)d_in[8];
    const float* b2  = (const float*)d_in[9];
    float* out = (float*)d_out;

    const size_t sm1 = (size_t)16241 * 4;   // 63.4 KB -> 3 blocks/SM
    const size_t sm2 = (size_t)14818 * 4;   // 57.9 KB -> 3 blocks/SM
    cudaFuncSetAttribute(gat_kernel, cudaFuncAttributeMaxDynamicSharedMemorySize, (int)sm1);
    cudaFuncSetAttribute(tcn_kernel, cudaFuncAttributeMaxDynamicSharedMemorySize, (int)sm2);

    gat_kernel<<<4096, 544, sm1>>>(x, adj, W, a);
    tcn_kernel<<<8192, 544, sm2>>>(x, w1, g1, b1, w2, g2, b2, out);
}

// round 7
// speedup vs baseline: 2.0560x; 1.2158x over previous
#include <cuda_runtime.h>
#include <math.h>

// B=64, N=17, T=512, C=64, H=4, DK=16
#define NB 64
#define NN 17
#define NT 512
#define NC 64

// Intermediate GAT output g[b,n,t,c] (flat per (b,n): t*64+c), 142.6 MB scratch.
__device__ float g_buf[(size_t)NB * NN * NT * NC];

// ---- packed fp32x2 helpers (Blackwell) ----
__device__ __forceinline__ unsigned long long pack2(float lo, float hi) {
    unsigned long long r;
    asm("mov.b64 %0,{%1,%2};" : "=l"(r) : "f"(lo), "f"(hi));
    return r;
}
__device__ __forceinline__ void unpack2(unsigned long long v, float& lo, float& hi) {
    asm("mov.b64 {%0,%1},%2;" : "=f"(lo), "=f"(hi) : "l"(v));
}
__device__ __forceinline__ unsigned long long fma2(unsigned long long a,
                                                   unsigned long long b,
                                                   unsigned long long c) {
    unsigned long long d;
    asm("fma.rn.f32x2 %0,%1,%2,%3;" : "=l"(d) : "l"(a), "l"(b), "l"(c));
    return d;
}

// Branchless erf-based GELU (Abramowitz-Stegun 7.1.26, |abs err| <= 1.5e-7).
__device__ __forceinline__ float gelu_fast(float v) {
    float av = fabsf(v);
    float s  = av * 0.70710678118654752440f;
    float d  = fmaf(0.3275911f, s, 1.0f);
    float t;
    asm("rcp.approx.f32 %0,%1;" : "=f"(t) : "f"(d));
    float e  = __expf(-s * s);
    float p  = fmaf(1.061405429f, t, -1.453152027f);
    p = fmaf(p, t, 1.421413741f);
    p = fmaf(p, t, -0.284496736f);
    p = fmaf(p, t, 0.254829592f);
    p = p * t;
    float u = fmaf(-p, e, 1.0f);          // erf(|v|/sqrt(2))
    return fmaf(0.5f * av, u, 0.5f * v);  // 0.5v + 0.5|v|erf
}

// =====================================================================
// K1: GAT.  One block per (b, t-chunk of 8).  grid 4096, 544 threads.
// h lives in registers (16 floats/thread); no hs array.
// No-max softmax (values bounded; masked terms underflow to exactly 0).
// smem floats: Wt 4224 | xs 8976 | av 32 | bias 289 |
//              ss/ts/rowR/scl 544 each  (= 15697 ~ 62.8KB) -> 3 blk/SM
// xs addr(n,f) = n*528 + (f>>6)*66 + (f&63)   (f = tl*64 + c)
// =====================================================================
extern "C" __global__ void __launch_bounds__(544, 3)
gat_kernel(const float* __restrict__ x, const int* __restrict__ adj,
           const float* __restrict__ W, const float* __restrict__ a)
{
    extern __shared__ float sm[];
    float* Wt   = sm;            // transposed: Wt[c*66 + o] = W[o][c]
    float* xs   = Wt + 4224;
    float* av   = xs + 8976;
    float* bias = av + 32;
    float* ss   = bias + 289;
    float* ts   = ss + 544;
    float* rowR = ts + 544;
    float* scl  = rowR + 544;

    const int tid = threadIdx.x;
    const int b   = blockIdx.x >> 6;
    const int t0  = (blockIdx.x & 63) * 8;

    // ---- P0: loads ----
    for (int i = tid; i < 4096; i += 544) {
        int o = i >> 6, c = i & 63;
        Wt[c * 66 + o] = W[i];
    }
    {   // x slab as float2: 4352 float2, 8 iters
        const float2* xb2 = (const float2*)x + (size_t)b * 278528 + t0 * 32;
        #pragma unroll
        for (int k = 0; k < 8; k++) {
            int i = tid + k * 544;
            int n = i >> 8, rem = i & 255;     // 256 float2 per node
            int tl = rem >> 5, cpl = rem & 31;
            float2 v = xb2[(size_t)n * 16384 + tl * 32 + cpl];
            ((float2*)xs)[n * 264 + tl * 33 + cpl] = v;
        }
    }
    if (tid < 32) av[tid] = a[tid];
    if (tid < 289)
        bias[tid] = (adj[b * 289 + tid] == 0) ? -1e9f : 0.0f;
    __syncthreads();

    // ---- P1: h = h0 @ W^T ; packed f32x2, h kept in registers ----
    const int og = tid & 15;     // output pairs (2og,2og+1) and (+32,+33)
    const int pg = tid >> 4;     // p = pg + 34*j, p = tl*17+n
    unsigned long long acc[2][4];
    int pb[4];
    {
        #pragma unroll
        for (int j = 0; j < 4; j++) {
            int p = pg + 34 * j;
            int n = p % 17, tl = p / 17;
            pb[j] = n * 528 + tl * 66;
            acc[0][j] = 0ULL; acc[1][j] = 0ULL;
        }
        const unsigned long long* w0p =
            (const unsigned long long*)(Wt + 2 * og);
        const unsigned long long* w1p =
            (const unsigned long long*)(Wt + 2 * og + 32);
        #pragma unroll 4
        for (int c = 0; c < 64; c++) {
            unsigned long long w0 = w0p[c * 33];   // 66 floats = 33 u64
            unsigned long long w1 = w1p[c * 33];
            #pragma unroll
            for (int j = 0; j < 4; j++) {
                float xv = xs[pb[j] + c];
                unsigned long long xv2 = pack2(xv, xv);
                acc[0][j] = fma2(w0, xv2, acc[0][j]);
                acc[1][j] = fma2(w1, xv2, acc[1][j]);
            }
        }
    }

    // ---- P2: s,t via in-warp 8-lane reductions of register h ----
    {
        const int h0 = og >> 3;            // head of pair (2og,2og+1); +2 for hi
        const int d0 = 2 * (og & 7);       // a-index within head
        const float aS0 = av[d0],      aS1 = av[d0 + 1];
        const float aT0 = av[16 + d0], aT1 = av[17 + d0];
        #pragma unroll
        for (int j = 0; j < 4; j++) {
            float hlo0, hhi0, hlo1, hhi1;
            unpack2(acc[0][j], hlo0, hhi0);
            unpack2(acc[1][j], hlo1, hhi1);
            float sA = fmaf(hlo0, aS0, hhi0 * aS1);
            float tA = fmaf(hlo0, aT0, hhi0 * aT1);
            float sB = fmaf(hlo1, aS0, hhi1 * aS1);
            float tB = fmaf(hlo1, aT0, hhi1 * aT1);
            #pragma unroll
            for (int w = 4; w; w >>= 1) {
                sA += __shfl_xor_sync(0xffffffffu, sA, w);
                tA += __shfl_xor_sync(0xffffffffu, tA, w);
                sB += __shfl_xor_sync(0xffffffffu, sB, w);
                tB += __shfl_xor_sync(0xffffffffu, tB, w);
            }
            if ((og & 7) == 0) {
                int p = pg + 34 * j;
                ss[p * 4 + h0]     = sA;
                ss[p * 4 + h0 + 2] = sB;
                ts[p * 4 + h0]     = tA;
                ts[p * 4 + h0 + 2] = tB;
            }
        }
    }
    __syncthreads();

    // ---- P3: row sums S_i (no max subtraction; masked -> exp underflows to 0)
    {
        int q = tid;
        int h = q & 3, p = q >> 2;
        int i = p % 17, tl = p / 17;
        float sv = ss[q];
        const float* tsr = ts + (tl * 17) * 4 + h;
        const float* br  = bias + i * 17;
        float S = 0.0f;
        #pragma unroll
        for (int j = 0; j < 17; j++) {
            float e = sv + tsr[j * 4];
            e = (e > 0.0f) ? e : 0.2f * e;
            S += __expf(e + br[j]);
        }
        // S==0 only if row fully masked: reference softmax -> uniform 1/17.
        rowR[q] = (S > 0.0f) ? 1.0f / S : -1.0f;
    }
    __syncthreads();

    // ---- P4: scale[tl,j,h] = sum_i alpha[i,j,h] ----
    {
        int q = tid;
        int h = q & 3, p = q >> 2;
        int jj = p % 17, tl = p / 17;
        float tv = ts[q];
        float acc4 = 0.0f;
        #pragma unroll
        for (int i = 0; i < 17; i++) {
            int qi = (tl * 17 + i) * 4 + h;
            float e = ss[qi] + tv;
            e = (e > 0.0f) ? e : 0.2f * e;
            float R = rowR[qi];
            float term = __expf(e + bias[i * 17 + jj]) * R;
            if (R < 0.0f) term = 0.05882352941176470588f;   // 1/17
            acc4 += term;
        }
        scl[q] = acc4;
    }
    __syncthreads();

    // ---- P5: g = h*scale + h0 -> g_buf directly from registers ----
    {
        const int h0 = og >> 3;
        float* gbase = g_buf + (size_t)b * 557056 + t0 * 64;
        #pragma unroll
        for (int j = 0; j < 4; j++) {
            int p = pg + 34 * j;
            int n = p % 17, tl = p / 17;
            float sc0 = scl[(tl * 17 + n) * 4 + h0];
            float sc2 = scl[(tl * 17 + n) * 4 + h0 + 2];
            float hlo0, hhi0, hlo1, hhi1;
            unpack2(acc[0][j], hlo0, hhi0);
            unpack2(acc[1][j], hlo1, hhi1);
            float2 x0 = *(const float2*)&xs[pb[j] + 2 * og];
            float2 x1 = *(const float2*)&xs[pb[j] + 2 * og + 32];
            float2 g0, g1;
            g0.x = fmaf(hlo0, sc0, x0.x);
            g0.y = fmaf(hhi0, sc0, x0.y);
            g1.x = fmaf(hlo1, sc2, x1.x);
            g1.y = fmaf(hhi1, sc2, x1.y);
            int base = n * 32768 + tl * 64;
            *(float2*)(gbase + base + 2 * og)      = g0;
            *(float2*)(gbase + base + 2 * og + 32) = g1;
        }
    }
}

// =====================================================================
// K2: causal depthwise TCN x2 on the reinterpreted [64,512] flat view
//     + output transpose + permuted residual.
// Block = (b, tau-chunk of 16, row-half).  544 threads, 1 row/thread,
// 16 outputs/thread via rolling windows (5-reg y, 3-reg g).
// smem floats: xs 17*522=8874 | gss 544*23=12512 | cw 640 (= 22026 ~ 88KB)
// =====================================================================
extern "C" __global__ void __launch_bounds__(544, 2)
tcn_kernel(const float* __restrict__ x,
           const float* __restrict__ w1, const float* __restrict__ gamma1,
           const float* __restrict__ beta1,
           const float* __restrict__ w2, const float* __restrict__ gamma2,
           const float* __restrict__ beta2,
           float* __restrict__ out)
{
    extern __shared__ float sm[];
    float* xs  = sm;             // [17][522] residual slab (16t x 32c used)
    float* gss = xs + 8874;      // [544][23] g halo (22 used, stride 23)
    float* cw  = gss + 12512;    // packed conv/BN params (640)

    const int tid  = threadIdx.x;
    const int bid  = blockIdx.x;
    const int half = bid & 1;               // row half
    const int tau0 = ((bid >> 1) & 31) * 16;
    const int b    = bid >> 6;

    // residual slab via float2: 17 n x 16 t x 16 c-pairs = 4352 fl2, 8 iters
    {
        const float2* xb2 = (const float2*)x + (size_t)b * 278528
                            + tau0 * 32 + half * 16;
        #pragma unroll
        for (int k = 0; k < 8; k++) {
            int i = tid + k * 544;
            int ns = i >> 8, rem = i & 255;     // 256 fl2 per node
            int kk = rem >> 4, cpl = rem & 15;
            float2 v = xb2[(size_t)ns * 16384 + kk * 32 + cpl];
            *(float2*)&xs[ns * 522 + kk * 32 + 2 * cpl] = v;
        }
    }
    for (int i = tid; i < 640; i += 544) {
        float v;
        if      (i < 192) v = w1[i];
        else if (i < 256) v = gamma1[i - 192];
        else if (i < 320) v = beta1[i - 256];
        else if (i < 512) v = w2[i - 320];
        else if (i < 576) v = gamma2[i - 512];
        else              v = beta2[i - 576];
        cw[i] = v;
    }
    // g halo: row rr needs flat cc*512 + [tau0-6, tau0+16) = 11 fl2.
    // 544*11 = 5984 fl2, exactly 11 iters.
    {
        const float2* gblk2 = (const float2*)(g_buf) + (size_t)b * 278528;
        const int toff = (tau0 - 6) >> 1;   // tau0-6 even
        #pragma unroll
        for (int k = 0; k < 11; k++) {
            int i = tid + k * 544;
            int rr = i / 11, jj = i - rr * 11;
            int rg = half * 544 + rr;
            int n = rg >> 6, cc = rg & 63;
            int tt = tau0 - 6 + 2 * jj;
            float2 v;
            if (tt >= 0)
                v = gblk2[n * 16384 + cc * 256 + toff + jj];
            else { v.x = 0.0f; v.y = 0.0f; }
            gss[rr * 23 + 2 * jj]     = v.x;
            gss[rr * 23 + 2 * jj + 1] = v.y;
        }
    }
    __syncthreads();

    const float rsb = 0.9999950000374997f;   // 1/sqrt(1 + 1e-5)
    {
        const int rr = tid;
        const int rg = half * 544 + rr;
        const int n  = rg >> 6, cc = rg & 63;
        const float gs1 = cw[192 + cc] * rsb;
        const float A0  = cw[cc * 3 + 0] * gs1;
        const float A1  = cw[cc * 3 + 1] * gs1;
        const float A2  = cw[cc * 3 + 2] * gs1;
        const float BB1 = cw[256 + cc];
        const float gs2 = cw[512 + cc] * rsb;
        const float C0  = cw[320 + cc * 3 + 0] * gs2;
        const float C1  = cw[320 + cc * 3 + 1] * gs2;
        const float C2  = cw[320 + cc * 3 + 2] * gs2;
        const float BB2 = cw[576 + cc];
        const float* gr = gss + rr * 23;   // gr[idx] = g[tau0-6+idx]

        const int ns  = rg % 17;
        const int csl = rg / 17 - half * 32;
        float* orow = out + ((size_t)(b * NN + n) * 512 + tau0) * 64 + cc;
        const float* xres = xs + ns * 522 + csl;

        float gm2 = gr[0], gm1 = gr[1];
        float y0 = 0.f, y1 = 0.f, y2 = 0.f, y3 = 0.f, y4 = 0.f;
        #pragma unroll
        for (int j = -4; j < 16; j++) {
            float g0 = gr[j + 6];
            float v = fmaf(A0, gm2, BB1);
            v = fmaf(A1, gm1, v);
            v = fmaf(A2, g0, v);
            float yn = gelu_fast(v);
            if (tau0 == 0 && j < 0) yn = 0.0f;   // causal zero-pad region
            y4 = y3; y3 = y2; y2 = y1; y1 = y0; y0 = yn;
            if (j >= 0) {
                float w = fmaf(C0, y4, BB2);
                w = fmaf(C1, y2, w);
                w = fmaf(C2, y0, w);
                float z = gelu_fast(w);
                orow[(size_t)j * 64] = z + xres[j * 32];
            }
            gm2 = gm1; gm1 = g0;
        }
    }
}

// =====================================================================
extern "C" void kernel_launch(void* const* d_in, const int* in_sizes, int n_in,
                              void* d_out, int out_size)
{
    const float* x   = (const float*)d_in[0];
    const int*   adj = (const int*)  d_in[1];
    const float* W   = (const float*)d_in[2];
    const float* a   = (const float*)d_in[3];
    const float* w1  = (const float*)d_in[4];
    const float* g1  = (const float*)d_in[5];
    const float* b1  = (const float*)d_in[6];
    const float* w2  = (const float*)d_in[7];
    const float* g2  = (const float*)d_in[8];
    const float* b2  = (const float*)d_in[9];
    float* out = (float*)d_out;

    const size_t sm1 = (size_t)15697 * 4;   // 62.8 KB -> 3 blocks/SM
    const size_t sm2 = (size_t)22026 * 4;   // 88.1 KB -> 2 blocks/SM
    cudaFuncSetAttribute(gat_kernel, cudaFuncAttributeMaxDynamicSharedMemorySize, (int)sm1);
    cudaFuncSetAttribute(tcn_kernel, cudaFuncAttributeMaxDynamicSharedMemorySize, (int)sm2);

    gat_kernel<<<4096, 544, sm1>>>(x, adj, W, a);
    tcn_kernel<<<4096, 544, sm2>>>(x, w1, g1, b1, w2, g2, b2, out);
}